// round 8
// baseline (speedup 1.0000x reference)
#include <cuda_runtime.h>

#define BB 16
#define NN 4096
#define CC 64
#define SS 1024
#define KNB 32

__device__ int g_idx[BB * SS * KNB];

typedef unsigned long long u64;

__device__ __forceinline__ u64 pack2(float a, float b) {
    u64 r;
    asm("mov.b64 %0, {%1, %2};" : "=l"(r) : "f"(a), "f"(b));
    return r;
}
__device__ __forceinline__ void unpack2(u64 v, float& a, float& b) {
    asm("mov.b64 {%0, %1}, %2;" : "=f"(a), "=f"(b) : "l"(v));
}
__device__ __forceinline__ void ffma2(u64& d, u64 a, u64 b) {
    asm("fma.rn.f32x2 %0, %1, %2, %0;" : "+l"(d) : "l"(a), "l"(b));
}
__device__ __forceinline__ u64 sub2(u64 a, u64 b) {
    u64 r;
    asm("sub.rn.f32x2 %0, %1, %2;" : "=l"(r) : "l"(a), "l"(b));
    return r;
}
__device__ __forceinline__ u64 mul2(u64 a, u64 b) {
    u64 r;
    asm("mul.rn.f32x2 %0, %1, %2;" : "=l"(r) : "l"(a), "l"(b));
    return r;
}
__device__ __forceinline__ u64 add2(u64 a, u64 b) {
    u64 r;
    asm("add.rn.f32x2 %0, %1, %2;" : "=l"(r) : "l"(a), "l"(b));
    return r;
}
__device__ __forceinline__ u64 u64max(u64 a, u64 b) { return a > b ? a : b; }

// ---------------------------------------------------------------------------
// Kernel 1: FPS. One block (256 thr) per batch; 16 pts/thread packed in regs.
// Exact per-lane rounding (packed rn = scalar rn). Reduction tail:
// REDUX max(value) -> IMNMX tree for own k -> REDUX min(gidx) -> 1 bar ->
// 8-key u64 tree. Centroid via broadcast LDS from SoA shared copy.
// ---------------------------------------------------------------------------
__global__ __launch_bounds__(256) void fps_kernel(const float* __restrict__ xyz,
                                                  float* __restrict__ out_xyz) {
    const int b = blockIdx.x;
    const float* x = xyz + (size_t)b * NN * 3;
    const int tid = threadIdx.x;
    const int lane = tid & 31, wid = tid >> 5;

    __shared__ float sxx[NN], sxy[NN], sxz[NN];
    __shared__ u64 skey[2][8];

    for (int j = tid; j < NN; j += 256) {
        sxx[j] = x[j * 3 + 0];
        sxy[j] = x[j * 3 + 1];
        sxz[j] = x[j * 3 + 2];
    }

    u64 pxp[8], pyp[8], pzp[8];
    float dmin[16];
#pragma unroll
    for (int p = 0; p < 8; p++) {
        int j = tid * 16 + 2 * p;
        pxp[p] = pack2(x[j * 3 + 0], x[j * 3 + 3]);
        pyp[p] = pack2(x[j * 3 + 1], x[j * 3 + 4]);
        pzp[p] = pack2(x[j * 3 + 2], x[j * 3 + 5]);
        dmin[2 * p] = 1e10f;
        dmin[2 * p + 1] = 1e10f;
    }
    __syncthreads();

    float ccx = sxx[0], ccy = sxy[0], ccz = sxz[0];

    for (int i = 0; i < SS; i++) {
        const int par = i & 1;
        if (tid == 0) {
            float* o = out_xyz + ((size_t)b * SS + i) * 3;
            o[0] = ccx; o[1] = ccy; o[2] = ccz;
        }
        u64 cx2 = pack2(ccx, ccx);
        u64 cy2 = pack2(ccy, ccy);
        u64 cz2 = pack2(ccz, ccz);

#pragma unroll
        for (int p = 0; p < 8; p++) {
            u64 sx = sub2(pxp[p], cx2);
            u64 sy = sub2(pyp[p], cy2);
            u64 sz = sub2(pzp[p], cz2);
            u64 dd = add2(add2(mul2(sx, sx), mul2(sy, sy)), mul2(sz, sz));
            float d0, d1;
            unpack2(dd, d0, d1);
            dmin[2 * p] = fminf(dmin[2 * p], d0);
            dmin[2 * p + 1] = fminf(dmin[2 * p + 1], d1);
        }
        // max tree over 16 dmin
        float m8[8];
#pragma unroll
        for (int t = 0; t < 8; t++) m8[t] = fmaxf(dmin[2 * t], dmin[2 * t + 1]);
        float m4a = fmaxf(m8[0], m8[1]), m4b = fmaxf(m8[2], m8[3]);
        float m4c = fmaxf(m8[4], m8[5]), m4d = fmaxf(m8[6], m8[7]);
        float bv = fmaxf(fmaxf(m4a, m4b), fmaxf(m4c, m4d));

        unsigned vb = __float_as_uint(bv);               // nonneg: bits monotone
        unsigned wm = __reduce_max_sync(0xffffffffu, vb);

        // first k with dmin[k]==wm (min tree; non-match -> 99)
        int ck[16];
#pragma unroll
        for (int k = 0; k < 16; k++)
            ck[k] = (__float_as_uint(dmin[k]) == wm) ? k : 99;
#pragma unroll
        for (int s = 8; s >= 1; s >>= 1)
#pragma unroll
            for (int k = 0; k < s; k++) ck[k] = min(ck[k], ck[k + s]);

        unsigned gcand = (vb == wm) ? (unsigned)(tid * 16 + ck[0]) : 0xFFFFu;
        unsigned widx = __reduce_min_sync(0xffffffffu, gcand);

        if (lane == 0)
            skey[par][wid] = ((u64)wm << 32) | (unsigned)(4095 - widx);
        __syncthreads();

        u64 k0 = skey[par][0], k1 = skey[par][1];
        u64 k2 = skey[par][2], k3 = skey[par][3];
        u64 k4 = skey[par][4], k5 = skey[par][5];
        u64 k6 = skey[par][6], k7 = skey[par][7];
        u64 mk = u64max(u64max(u64max(k0, k1), u64max(k2, k3)),
                        u64max(u64max(k4, k5), u64max(k6, k7)));
        int far = 4095 - (int)(unsigned)mk;

        ccx = sxx[far];
        ccy = sxy[far];
        ccz = sxz[far];
    }
}

// ---------------------------------------------------------------------------
// Kernel 2: ball query (unchanged, exact math).
// ---------------------------------------------------------------------------
__global__ __launch_bounds__(256) void qb_kernel(const float* __restrict__ xyz,
                                                 const float* __restrict__ new_xyz) {
    const int gw = (blockIdx.x * blockDim.x + threadIdx.x) >> 5;
    const int lane = threadIdx.x & 31;
    if (gw >= BB * SS) return;
    const int b = gw >> 10;
    const float* x = xyz + (size_t)b * NN * 3;
    const float cx = new_xyz[gw * 3 + 0];
    const float cy = new_xyz[gw * 3 + 1];
    const float cz = new_xyz[gw * 3 + 2];
    int* o = g_idx + (size_t)gw * KNB;

    const float r2 = 0.04f;
    int cnt = 0;
    int first = 0;
    bool have = false;
    for (int j0 = 0; j0 < NN; j0 += 32) {
        int j = j0 + lane;
        float dx = x[j * 3 + 0] - cx;
        float dy = x[j * 3 + 1] - cy;
        float dz = x[j * 3 + 2] - cz;
        float d = __fadd_rn(__fadd_rn(__fmul_rn(dx, dx), __fmul_rn(dy, dy)),
                            __fmul_rn(dz, dz));
        bool in = (d <= r2);
        unsigned m = __ballot_sync(0xffffffffu, in);
        if (!have && m) { first = j0 + __ffs(m) - 1; have = true; }
        int pre = __popc(m & ((1u << lane) - 1u));
        if (in) {
            int p = cnt + pre;
            if (p < KNB) o[p] = j;
        }
        cnt += __popc(m);
        if (cnt >= KNB) break;
    }
    for (int p = cnt + lane; p < KNB; p += 32) o[p] = first;
}

// ---------------------------------------------------------------------------
// Kernel 3: gather + MLP + maxpool. 64 threads per site. Weights loaded as
// natural u64 feature-pairs (no packing); activations splatted. Per-scalar
// accumulation order over c unchanged -> bit-exact vs previous kernels.
// Stage0/1: thread = (fg 0..7 -> 8 feats, rg 0..7 -> 4 rows); 16 ffma2/c.
// Stage2:   thread = (fg 0..15 -> 8 feats, rg 0..3 -> 8 rows); 32 ffma2/c.
// ---------------------------------------------------------------------------
__global__ __launch_bounds__(64) void mlp_kernel(
    const float* __restrict__ xyz, const float* __restrict__ points,
    const float* __restrict__ new_xyz,
    const float* __restrict__ w0, const float* __restrict__ b0,
    const float* __restrict__ w1, const float* __restrict__ b1,
    const float* __restrict__ w2, const float* __restrict__ b2,
    float* __restrict__ out_points) {
    const int gw = blockIdx.x;  // b*S + s
    const int b = gw >> 10;
    const int tid = threadIdx.x;
    const int lane = tid & 31, wid = tid >> 5;

    __shared__ __align__(16) float sX[67 * 36];  // stage0 in; stage1 out alias
    __shared__ __align__(16) float sH[64 * 36];  // stage0 out / stage1 in
    __shared__ __align__(16) float smax[4][128];
    __shared__ int sidx[KNB];
    __shared__ float sc[3];

    if (tid < KNB) sidx[tid] = g_idx[(size_t)gw * KNB + tid];
    if (tid < 3) sc[tid] = new_xyz[gw * 3 + tid];
    __syncthreads();

    // gather (col-major [c][r], stride 36); 2 warps cover 32 rows
    for (int r = wid; r < KNB; r += 2) {
        int id = sidx[r];
        const float* p = points + ((size_t)b * NN + id) * CC;
        float v0 = p[lane];
        float v1 = p[32 + lane];
        sX[lane * 36 + r] = v0;
        sX[(32 + lane) * 36 + r] = v1;
        if (lane < 3)
            sX[(64 + lane) * 36 + r] =
                xyz[((size_t)b * NN + id) * 3 + lane] - sc[lane];
    }
    __syncthreads();

    // ---- stage 0: 67 -> 64 ----
    {
        const int f0 = (tid & 7) * 8;    // 8 features f0..f0+7 (4 pairs)
        const int r0 = (tid >> 3) * 4;   // 4 rows
        u64 acc[4][4];
#pragma unroll
        for (int p = 0; p < 4; p++)
#pragma unroll
            for (int r = 0; r < 4; r++) acc[p][r] = 0ull;
#pragma unroll 4
        for (int c = 0; c < 67; c++) {
            ulonglong2 wA = *(const ulonglong2*)(w0 + c * 64 + f0);
            ulonglong2 wB = *(const ulonglong2*)(w0 + c * 64 + f0 + 4);
            float4 av = *(const float4*)(sX + c * 36 + r0);
            u64 a0 = pack2(av.x, av.x), a1 = pack2(av.y, av.y);
            u64 a2 = pack2(av.z, av.z), a3 = pack2(av.w, av.w);
            ffma2(acc[0][0], a0, wA.x); ffma2(acc[0][1], a1, wA.x);
            ffma2(acc[0][2], a2, wA.x); ffma2(acc[0][3], a3, wA.x);
            ffma2(acc[1][0], a0, wA.y); ffma2(acc[1][1], a1, wA.y);
            ffma2(acc[1][2], a2, wA.y); ffma2(acc[1][3], a3, wA.y);
            ffma2(acc[2][0], a0, wB.x); ffma2(acc[2][1], a1, wB.x);
            ffma2(acc[2][2], a2, wB.x); ffma2(acc[2][3], a3, wB.x);
            ffma2(acc[3][0], a0, wB.y); ffma2(acc[3][1], a1, wB.y);
            ffma2(acc[3][2], a2, wB.y); ffma2(acc[3][3], a3, wB.y);
        }
        ulonglong2 bA = *(const ulonglong2*)(b0 + f0);
        ulonglong2 bB = *(const ulonglong2*)(b0 + f0 + 4);
        u64 bp[4] = {bA.x, bA.y, bB.x, bB.y};
#pragma unroll
        for (int p = 0; p < 4; p++) {
            float lo[4], hi[4];
#pragma unroll
            for (int r = 0; r < 4; r++) {
                u64 v = add2(acc[p][r], bp[p]);
                unpack2(v, lo[r], hi[r]);
                lo[r] = fmaxf(lo[r], 0.0f);
                hi[r] = fmaxf(hi[r], 0.0f);
            }
            *(float4*)(sH + (f0 + 2 * p) * 36 + r0) =
                make_float4(lo[0], lo[1], lo[2], lo[3]);
            *(float4*)(sH + (f0 + 2 * p + 1) * 36 + r0) =
                make_float4(hi[0], hi[1], hi[2], hi[3]);
        }
    }
    __syncthreads();

    // ---- stage 1: 64 -> 64 (sH -> sX alias) ----
    {
        const int f0 = (tid & 7) * 8;
        const int r0 = (tid >> 3) * 4;
        u64 acc[4][4];
#pragma unroll
        for (int p = 0; p < 4; p++)
#pragma unroll
            for (int r = 0; r < 4; r++) acc[p][r] = 0ull;
#pragma unroll 4
        for (int c = 0; c < 64; c++) {
            ulonglong2 wA = *(const ulonglong2*)(w1 + c * 64 + f0);
            ulonglong2 wB = *(const ulonglong2*)(w1 + c * 64 + f0 + 4);
            float4 av = *(const float4*)(sH + c * 36 + r0);
            u64 a0 = pack2(av.x, av.x), a1 = pack2(av.y, av.y);
            u64 a2 = pack2(av.z, av.z), a3 = pack2(av.w, av.w);
            ffma2(acc[0][0], a0, wA.x); ffma2(acc[0][1], a1, wA.x);
            ffma2(acc[0][2], a2, wA.x); ffma2(acc[0][3], a3, wA.x);
            ffma2(acc[1][0], a0, wA.y); ffma2(acc[1][1], a1, wA.y);
            ffma2(acc[1][2], a2, wA.y); ffma2(acc[1][3], a3, wA.y);
            ffma2(acc[2][0], a0, wB.x); ffma2(acc[2][1], a1, wB.x);
            ffma2(acc[2][2], a2, wB.x); ffma2(acc[2][3], a3, wB.x);
            ffma2(acc[3][0], a0, wB.y); ffma2(acc[3][1], a1, wB.y);
            ffma2(acc[3][2], a2, wB.y); ffma2(acc[3][3], a3, wB.y);
        }
        ulonglong2 bA = *(const ulonglong2*)(b1 + f0);
        ulonglong2 bB = *(const ulonglong2*)(b1 + f0 + 4);
        u64 bp[4] = {bA.x, bA.y, bB.x, bB.y};
#pragma unroll
        for (int p = 0; p < 4; p++) {
            float lo[4], hi[4];
#pragma unroll
            for (int r = 0; r < 4; r++) {
                u64 v = add2(acc[p][r], bp[p]);
                unpack2(v, lo[r], hi[r]);
                lo[r] = fmaxf(lo[r], 0.0f);
                hi[r] = fmaxf(hi[r], 0.0f);
            }
            *(float4*)(sX + (f0 + 2 * p) * 36 + r0) =
                make_float4(lo[0], lo[1], lo[2], lo[3]);
            *(float4*)(sX + (f0 + 2 * p + 1) * 36 + r0) =
                make_float4(hi[0], hi[1], hi[2], hi[3]);
        }
    }
    __syncthreads();

    // ---- stage 2: 64 -> 128, partial maxpool over 8 rows per thread ----
    {
        const int f0 = (tid & 15) * 8;   // 8 features of 128 (4 pairs)
        const int r0 = (tid >> 4) * 8;   // 8 rows
        u64 acc[4][8];
#pragma unroll
        for (int p = 0; p < 4; p++)
#pragma unroll
            for (int r = 0; r < 8; r++) acc[p][r] = 0ull;
#pragma unroll 2
        for (int c = 0; c < 64; c++) {
            ulonglong2 wA = *(const ulonglong2*)(w2 + c * 128 + f0);
            ulonglong2 wB = *(const ulonglong2*)(w2 + c * 128 + f0 + 4);
            float4 u = *(const float4*)(sX + c * 36 + r0);
            float4 v = *(const float4*)(sX + c * 36 + r0 + 4);
            u64 a[8];
            a[0] = pack2(u.x, u.x); a[1] = pack2(u.y, u.y);
            a[2] = pack2(u.z, u.z); a[3] = pack2(u.w, u.w);
            a[4] = pack2(v.x, v.x); a[5] = pack2(v.y, v.y);
            a[6] = pack2(v.z, v.z); a[7] = pack2(v.w, v.w);
#pragma unroll
            for (int r = 0; r < 8; r++) {
                ffma2(acc[0][r], a[r], wA.x);
                ffma2(acc[1][r], a[r], wA.y);
                ffma2(acc[2][r], a[r], wB.x);
                ffma2(acc[3][r], a[r], wB.y);
            }
        }
        ulonglong2 bA = *(const ulonglong2*)(b2 + f0);
        ulonglong2 bB = *(const ulonglong2*)(b2 + f0 + 4);
        u64 bp[4] = {bA.x, bA.y, bB.x, bB.y};
        const int rg = tid >> 4;
#pragma unroll
        for (int p = 0; p < 4; p++) {
            float mlo = 0.0f, mhi = 0.0f;
#pragma unroll
            for (int r = 0; r < 8; r++) {
                u64 v = add2(acc[p][r], bp[p]);
                float lo, hi;
                unpack2(v, lo, hi);
                mlo = fmaxf(mlo, fmaxf(lo, 0.0f));
                mhi = fmaxf(mhi, fmaxf(hi, 0.0f));
            }
            smax[rg][f0 + 2 * p] = mlo;
            smax[rg][f0 + 2 * p + 1] = mhi;
        }
    }
    __syncthreads();
    {
        float m0 = fmaxf(fmaxf(smax[0][tid], smax[1][tid]),
                         fmaxf(smax[2][tid], smax[3][tid]));
        float m1 = fmaxf(fmaxf(smax[0][tid + 64], smax[1][tid + 64]),
                         fmaxf(smax[2][tid + 64], smax[3][tid + 64]));
        out_points[(size_t)gw * 128 + tid] = m0;
        out_points[(size_t)gw * 128 + tid + 64] = m1;
    }
}

extern "C" void kernel_launch(void* const* d_in, const int* in_sizes, int n_in,
                              void* d_out, int out_size) {
    const float* xyz = (const float*)d_in[0];
    const float* points = (const float*)d_in[1];
    const float* w0 = (const float*)d_in[2];
    const float* b0 = (const float*)d_in[3];
    const float* w1 = (const float*)d_in[4];
    const float* b1 = (const float*)d_in[5];
    const float* w2 = (const float*)d_in[6];
    const float* b2 = (const float*)d_in[7];

    float* out = (float*)d_out;
    float* new_xyz = out;                   // [B, S, 3]
    float* new_points = out + BB * SS * 3;  // [B, S, 128]

    fps_kernel<<<BB, 256>>>(xyz, new_xyz);
    qb_kernel<<<(BB * SS * 32 + 255) / 256, 256>>>(xyz, new_xyz);
    mlp_kernel<<<BB * SS, 64>>>(xyz, points, new_xyz,
                                w0, b0, w1, b1, w2, b2, new_points);
}

// round 12
// speedup vs baseline: 1.9045x; 1.9045x over previous
#include <cuda_runtime.h>

#define BB 16
#define NN 4096
#define CC 64
#define SS 1024
#define KNB 32

__device__ int g_idx[BB * SS * KNB];

typedef unsigned long long u64;

__device__ __forceinline__ u64 pack2(float a, float b) {
    u64 r;
    asm("mov.b64 %0, {%1, %2};" : "=l"(r) : "f"(a), "f"(b));
    return r;
}
__device__ __forceinline__ void unpack2(u64 v, float& a, float& b) {
    asm("mov.b64 {%0, %1}, %2;" : "=f"(a), "=f"(b) : "l"(v));
}
__device__ __forceinline__ void ffma2(u64& d, u64 a, u64 b) {
    asm("fma.rn.f32x2 %0, %1, %2, %0;" : "+l"(d) : "l"(a), "l"(b));
}
__device__ __forceinline__ u64 sub2(u64 a, u64 b) {
    u64 r;
    asm("sub.rn.f32x2 %0, %1, %2;" : "=l"(r) : "l"(a), "l"(b));
    return r;
}
__device__ __forceinline__ u64 mul2(u64 a, u64 b) {
    u64 r;
    asm("mul.rn.f32x2 %0, %1, %2;" : "=l"(r) : "l"(a), "l"(b));
    return r;
}
__device__ __forceinline__ u64 add2(u64 a, u64 b) {
    u64 r;
    asm("add.rn.f32x2 %0, %1, %2;" : "=l"(r) : "l"(a), "l"(b));
    return r;
}
__device__ __forceinline__ u64 u64max(u64 a, u64 b) { return a > b ? a : b; }

// ---------------------------------------------------------------------------
// Kernel 1: FPS (R4 structure, measured 401us). One block (256 thr) per batch;
// 16 points/thread packed in registers. Packed f32x2 distance (bit-identical
// per-lane rounding to scalar). Tail: REDUX max + ballot + shfl, 1 barrier,
// 8-key u64 tree. Only delta vs R4: centroid fetched via broadcast LDS from
// a shared SoA copy (grid=16 -> 1 block/SM, smem is free).
// ---------------------------------------------------------------------------
__global__ __launch_bounds__(256) void fps_kernel(const float* __restrict__ xyz,
                                                  float* __restrict__ out_xyz) {
    const int b = blockIdx.x;
    const float* x = xyz + (size_t)b * NN * 3;
    const int tid = threadIdx.x;
    const int lane = tid & 31, wid = tid >> 5;

    __shared__ float sxx[NN], sxy[NN], sxz[NN];
    __shared__ u64 skey[2][8];

    u64 pxp[8], pyp[8], pzp[8];
    float dmin[16];
#pragma unroll
    for (int p = 0; p < 8; p++) {
        int j = tid * 16 + 2 * p;
        pxp[p] = pack2(x[j * 3 + 0], x[j * 3 + 3]);
        pyp[p] = pack2(x[j * 3 + 1], x[j * 3 + 4]);
        pzp[p] = pack2(x[j * 3 + 2], x[j * 3 + 5]);
        dmin[2 * p] = 1e10f;
        dmin[2 * p + 1] = 1e10f;
    }
#pragma unroll
    for (int p = 0; p < 8; p++) {
        int j = tid * 16 + 2 * p;
        float a0, a1;
        unpack2(pxp[p], a0, a1); sxx[j] = a0; sxx[j + 1] = a1;
        unpack2(pyp[p], a0, a1); sxy[j] = a0; sxy[j + 1] = a1;
        unpack2(pzp[p], a0, a1); sxz[j] = a0; sxz[j + 1] = a1;
    }
    __syncthreads();

    float ccx = sxx[0], ccy = sxy[0], ccz = sxz[0];

    for (int i = 0; i < SS; i++) {
        const int par = i & 1;
        if (tid == 0) {
            float* o = out_xyz + ((size_t)b * SS + i) * 3;
            o[0] = ccx; o[1] = ccy; o[2] = ccz;
        }
        u64 cx2 = pack2(ccx, ccx);
        u64 cy2 = pack2(ccy, ccy);
        u64 cz2 = pack2(ccz, ccz);

        float bva = -1.0f, bvb = -1.0f;
#pragma unroll
        for (int p = 0; p < 8; p++) {
            u64 sx = sub2(pxp[p], cx2);
            u64 sy = sub2(pyp[p], cy2);
            u64 sz = sub2(pzp[p], cz2);
            u64 dd = add2(add2(mul2(sx, sx), mul2(sy, sy)), mul2(sz, sz));
            float d0, d1;
            unpack2(dd, d0, d1);
            dmin[2 * p] = fminf(dmin[2 * p], d0);
            dmin[2 * p + 1] = fminf(dmin[2 * p + 1], d1);
            bva = fmaxf(bva, dmin[2 * p]);
            bvb = fmaxf(bvb, dmin[2 * p + 1]);
        }
        float bv = fmaxf(bva, bvb);

        unsigned vb = __float_as_uint(bv);              // nonneg: bits monotone
        unsigned wm = __reduce_max_sync(0xffffffffu, vb);
        unsigned bal = __ballot_sync(0xffffffffu, vb == wm);
        int src = __ffs(bal) - 1;                       // lowest lane = lowest idx

        // all lanes search (only src's result used); descending -> lowest k wins
        int ck = 0;
#pragma unroll
        for (int k = 15; k >= 1; k--)
            if (__float_as_uint(dmin[k]) == wm) ck = k;

        int gidx = (wid * 32 + src) * 16 + __shfl_sync(0xffffffffu, ck, src);
        if (lane == 0)
            skey[par][wid] = ((u64)wm << 32) | (unsigned)(4095 - gidx);
        __syncthreads();

        u64 k0 = skey[par][0], k1 = skey[par][1];
        u64 k2 = skey[par][2], k3 = skey[par][3];
        u64 k4 = skey[par][4], k5 = skey[par][5];
        u64 k6 = skey[par][6], k7 = skey[par][7];
        u64 mk = u64max(u64max(u64max(k0, k1), u64max(k2, k3)),
                        u64max(u64max(k4, k5), u64max(k6, k7)));
        int far = 4095 - (int)(unsigned)mk;

        ccx = sxx[far];
        ccy = sxy[far];
        ccz = sxz[far];
    }
}

// ---------------------------------------------------------------------------
// Kernel 2: ball query (unchanged, exact math).
// ---------------------------------------------------------------------------
__global__ __launch_bounds__(256) void qb_kernel(const float* __restrict__ xyz,
                                                 const float* __restrict__ new_xyz) {
    const int gw = (blockIdx.x * blockDim.x + threadIdx.x) >> 5;
    const int lane = threadIdx.x & 31;
    if (gw >= BB * SS) return;
    const int b = gw >> 10;
    const float* x = xyz + (size_t)b * NN * 3;
    const float cx = new_xyz[gw * 3 + 0];
    const float cy = new_xyz[gw * 3 + 1];
    const float cz = new_xyz[gw * 3 + 2];
    int* o = g_idx + (size_t)gw * KNB;

    const float r2 = 0.04f;
    int cnt = 0;
    int first = 0;
    bool have = false;
    for (int j0 = 0; j0 < NN; j0 += 32) {
        int j = j0 + lane;
        float dx = x[j * 3 + 0] - cx;
        float dy = x[j * 3 + 1] - cy;
        float dz = x[j * 3 + 2] - cz;
        float d = __fadd_rn(__fadd_rn(__fmul_rn(dx, dx), __fmul_rn(dy, dy)),
                            __fmul_rn(dz, dz));
        bool in = (d <= r2);
        unsigned m = __ballot_sync(0xffffffffu, in);
        if (!have && m) { first = j0 + __ffs(m) - 1; have = true; }
        int pre = __popc(m & ((1u << lane) - 1u));
        if (in) {
            int p = cnt + pre;
            if (p < KNB) o[p] = j;
        }
        cnt += __popc(m);
        if (cnt >= KNB) break;
    }
    for (int p = cnt + lane; p < KNB; p += 32) o[p] = first;
}

// ---------------------------------------------------------------------------
// Kernel 3: gather + MLP + maxpool (exact R4 version, measured ~390us).
// Packed f32x2, 2 features per thread, 128 threads, stage1 aliases sX.
// Bit-exact accumulation order.
// ---------------------------------------------------------------------------
__global__ __launch_bounds__(128) void mlp_kernel(
    const float* __restrict__ xyz, const float* __restrict__ points,
    const float* __restrict__ new_xyz,
    const float* __restrict__ w0, const float* __restrict__ b0,
    const float* __restrict__ w1, const float* __restrict__ b1,
    const float* __restrict__ w2, const float* __restrict__ b2,
    float* __restrict__ out_points) {
    const int gw = blockIdx.x;  // b*S + s
    const int b = gw >> 10;
    const int tid = threadIdx.x;
    const int lane = tid & 31, wid = tid >> 5;

    __shared__ __align__(16) float sX[67 * 36];  // stage0 in; stage1 out (alias)
    __shared__ __align__(16) float sH[64 * 36];  // stage0 out / stage1 in
    __shared__ __align__(16) float smax[2][128];
    __shared__ int sidx[KNB];
    __shared__ float sc[3];

    if (tid < KNB) sidx[tid] = g_idx[(size_t)gw * KNB + tid];
    if (tid < 3) sc[tid] = new_xyz[gw * 3 + tid];
    __syncthreads();

    // gather (col-major [c][r], stride 36)
    for (int r = wid; r < KNB; r += 4) {
        int id = sidx[r];
        const float* p = points + ((size_t)b * NN + id) * CC;
        float v0 = p[lane];
        float v1 = p[32 + lane];
        sX[lane * 36 + r] = v0;
        sX[(32 + lane) * 36 + r] = v1;
        if (lane < 3)
            sX[(64 + lane) * 36 + r] =
                xyz[((size_t)b * NN + id) * 3 + lane] - sc[lane];
    }
    __syncthreads();

    // stage 0: 67 -> 64. thread = (feature-pair fp, row-octet rh)
    {
        const int fp = tid & 31;        // features fp, fp+32
        const int rh = tid >> 5;        // rows rh*8 .. rh*8+7
        u64 acc[8];
#pragma unroll
        for (int t = 0; t < 8; t++) acc[t] = 0ull;
#pragma unroll 4
        for (int c = 0; c < 67; c++) {
            float wa = w0[c * 64 + fp];
            float wb = w0[c * 64 + fp + 32];
            u64 wa2 = pack2(wa, wa);
            u64 wb2 = pack2(wb, wb);
            const ulonglong2* xp = (const ulonglong2*)(sX + c * 36 + rh * 8);
            ulonglong2 u0 = xp[0], u1 = xp[1];
            ffma2(acc[0], u0.x, wa2); ffma2(acc[1], u0.y, wa2);
            ffma2(acc[2], u1.x, wa2); ffma2(acc[3], u1.y, wa2);
            ffma2(acc[4], u0.x, wb2); ffma2(acc[5], u0.y, wb2);
            ffma2(acc[6], u1.x, wb2); ffma2(acc[7], u1.y, wb2);
        }
        float ba = b0[fp], bbv = b0[fp + 32];
#pragma unroll
        for (int t = 0; t < 4; t++) {
            float a0, a1;
            unpack2(acc[t], a0, a1);
            *(float2*)(sH + fp * 36 + rh * 8 + 2 * t) =
                make_float2(fmaxf(a0 + ba, 0.0f), fmaxf(a1 + ba, 0.0f));
            unpack2(acc[4 + t], a0, a1);
            *(float2*)(sH + (fp + 32) * 36 + rh * 8 + 2 * t) =
                make_float2(fmaxf(a0 + bbv, 0.0f), fmaxf(a1 + bbv, 0.0f));
        }
    }
    __syncthreads();

    // stage 1: 64 -> 64 (reads sH, writes sX alias)
    {
        const int fp = tid & 31;
        const int rh = tid >> 5;
        u64 acc[8];
#pragma unroll
        for (int t = 0; t < 8; t++) acc[t] = 0ull;
#pragma unroll 4
        for (int c = 0; c < 64; c++) {
            float wa = w1[c * 64 + fp];
            float wb = w1[c * 64 + fp + 32];
            u64 wa2 = pack2(wa, wa);
            u64 wb2 = pack2(wb, wb);
            const ulonglong2* xp = (const ulonglong2*)(sH + c * 36 + rh * 8);
            ulonglong2 u0 = xp[0], u1 = xp[1];
            ffma2(acc[0], u0.x, wa2); ffma2(acc[1], u0.y, wa2);
            ffma2(acc[2], u1.x, wa2); ffma2(acc[3], u1.y, wa2);
            ffma2(acc[4], u0.x, wb2); ffma2(acc[5], u0.y, wb2);
            ffma2(acc[6], u1.x, wb2); ffma2(acc[7], u1.y, wb2);
        }
        float ba = b1[fp], bbv = b1[fp + 32];
#pragma unroll
        for (int t = 0; t < 4; t++) {
            float a0, a1;
            unpack2(acc[t], a0, a1);
            *(float2*)(sX + fp * 36 + rh * 8 + 2 * t) =
                make_float2(fmaxf(a0 + ba, 0.0f), fmaxf(a1 + ba, 0.0f));
            unpack2(acc[4 + t], a0, a1);
            *(float2*)(sX + (fp + 32) * 36 + rh * 8 + 2 * t) =
                make_float2(fmaxf(a0 + bbv, 0.0f), fmaxf(a1 + bbv, 0.0f));
        }
    }
    __syncthreads();

    // stage 2: 64 -> 128, partial maxpool over 16 rows per thread-group
    {
        const int fp = tid & 63;        // features fp, fp+64
        const int rhh = tid >> 6;       // rows rhh*16 .. +15
        u64 acc[16];
#pragma unroll
        for (int t = 0; t < 16; t++) acc[t] = 0ull;
#pragma unroll 4
        for (int c = 0; c < 64; c++) {
            float wa = w2[c * 128 + fp];
            float wb = w2[c * 128 + fp + 64];
            u64 wa2 = pack2(wa, wa);
            u64 wb2 = pack2(wb, wb);
            const ulonglong2* gp = (const ulonglong2*)(sX + c * 36 + rhh * 16);
            ulonglong2 u0 = gp[0], u1 = gp[1], u2 = gp[2], u3 = gp[3];
            ffma2(acc[0], u0.x, wa2); ffma2(acc[1], u0.y, wa2);
            ffma2(acc[2], u1.x, wa2); ffma2(acc[3], u1.y, wa2);
            ffma2(acc[4], u2.x, wa2); ffma2(acc[5], u2.y, wa2);
            ffma2(acc[6], u3.x, wa2); ffma2(acc[7], u3.y, wa2);
            ffma2(acc[8],  u0.x, wb2); ffma2(acc[9],  u0.y, wb2);
            ffma2(acc[10], u1.x, wb2); ffma2(acc[11], u1.y, wb2);
            ffma2(acc[12], u2.x, wb2); ffma2(acc[13], u2.y, wb2);
            ffma2(acc[14], u3.x, wb2); ffma2(acc[15], u3.y, wb2);
        }
        float ba = b2[fp], bbv = b2[fp + 64];
        float ma = 0.0f, mb = 0.0f;
#pragma unroll
        for (int t = 0; t < 8; t++) {
            float a0, a1;
            unpack2(acc[t], a0, a1);
            ma = fmaxf(ma, fmaxf(a0 + ba, 0.0f));
            ma = fmaxf(ma, fmaxf(a1 + ba, 0.0f));
            unpack2(acc[8 + t], a0, a1);
            mb = fmaxf(mb, fmaxf(a0 + bbv, 0.0f));
            mb = fmaxf(mb, fmaxf(a1 + bbv, 0.0f));
        }
        smax[rhh][fp] = ma;
        smax[rhh][fp + 64] = mb;
    }
    __syncthreads();
    {
        float m = fmaxf(smax[0][tid], smax[1][tid]);
        out_points[(size_t)gw * 128 + tid] = m;
    }
}

extern "C" void kernel_launch(void* const* d_in, const int* in_sizes, int n_in,
                              void* d_out, int out_size) {
    const float* xyz = (const float*)d_in[0];
    const float* points = (const float*)d_in[1];
    const float* w0 = (const float*)d_in[2];
    const float* b0 = (const float*)d_in[3];
    const float* w1 = (const float*)d_in[4];
    const float* b1 = (const float*)d_in[5];
    const float* w2 = (const float*)d_in[6];
    const float* b2 = (const float*)d_in[7];

    float* out = (float*)d_out;
    float* new_xyz = out;                   // [B, S, 3]
    float* new_points = out + BB * SS * 3;  // [B, S, 128]

    fps_kernel<<<BB, 256>>>(xyz, new_xyz);
    qb_kernel<<<(BB * SS * 32 + 255) / 256, 256>>>(xyz, new_xyz);
    mlp_kernel<<<BB * SS, 128>>>(xyz, points, new_xyz,
                                 w0, b0, w1, b1, w2, b2, new_points);
}

// round 15
// speedup vs baseline: 2.3311x; 1.2240x over previous
#include <cuda_runtime.h>
#include <cuda_bf16.h>
#include <cstdint>

#define BB 16
#define NN 4096
#define CC 64
#define SS 1024
#define KNB 32

__device__ int g_idx[BB * SS * KNB];
__device__ __align__(16) unsigned char g_wimg[69632];  // pre-split packed weights

typedef unsigned long long u64;

// ---------------- packed f32x2 helpers (FPS) ----------------
__device__ __forceinline__ u64 pack2(float a, float b) {
    u64 r; asm("mov.b64 %0, {%1, %2};" : "=l"(r) : "f"(a), "f"(b)); return r;
}
__device__ __forceinline__ void unpack2(u64 v, float& a, float& b) {
    asm("mov.b64 {%0, %1}, %2;" : "=f"(a), "=f"(b) : "l"(v));
}
__device__ __forceinline__ u64 sub2(u64 a, u64 b) {
    u64 r; asm("sub.rn.f32x2 %0, %1, %2;" : "=l"(r) : "l"(a), "l"(b)); return r;
}
__device__ __forceinline__ u64 mul2(u64 a, u64 b) {
    u64 r; asm("mul.rn.f32x2 %0, %1, %2;" : "=l"(r) : "l"(a), "l"(b)); return r;
}
__device__ __forceinline__ u64 add2(u64 a, u64 b) {
    u64 r; asm("add.rn.f32x2 %0, %1, %2;" : "=l"(r) : "l"(a), "l"(b)); return r;
}
__device__ __forceinline__ u64 u64max(u64 a, u64 b) { return a > b ? a : b; }

// ---------------- bf16 split + mma helpers ----------------
__device__ __forceinline__ void split_bf16(float v, unsigned short& h,
                                           unsigned short& l) {
    __nv_bfloat16 hb = __float2bfloat16_rn(v);
    float hf = __bfloat162float(hb);
    __nv_bfloat16 lb = __float2bfloat16_rn(v - hf);
    h = *reinterpret_cast<unsigned short*>(&hb);
    l = *reinterpret_cast<unsigned short*>(&lb);
}
__device__ __forceinline__ void mma16816(float* d, const uint32_t* a,
                                         uint32_t b0, uint32_t b1) {
    asm volatile(
        "mma.sync.aligned.m16n8k16.row.col.f32.bf16.bf16.f32 "
        "{%0,%1,%2,%3}, {%4,%5,%6,%7}, {%8,%9}, {%0,%1,%2,%3};"
        : "+f"(d[0]), "+f"(d[1]), "+f"(d[2]), "+f"(d[3])
        : "r"(a[0]), "r"(a[1]), "r"(a[2]), "r"(a[3]), "r"(b0), "r"(b1));
}

// A tile: row stride 144B (36 words -> conflict-free frag loads)
#define A_STRIDE 144
// W image: row stride 136B
#define W_STRIDE 136
#define W_S0H 0
#define W_S0L 8704
#define W_S1H 17408
#define W_S1L 26112
#define W_S2H 34816
#define W_S2L 52224
#define W_BYTES 69632

// smem layout (dynamic)
#define SM_AHI 0
#define SM_ALO 18432
#define SM_W 36864
#define SM_RX (SM_W + W_BYTES)          /* 128 f */
#define SM_RY (SM_RX + 512)
#define SM_RZ (SM_RY + 512)
#define SM_WX (SM_RZ + 512)             /* 64 f each */
#define SM_WY (SM_WX + 256)
#define SM_WZ (SM_WY + 256)
#define SM_B0 (SM_WZ + 256)
#define SM_B1 (SM_B0 + 256)
#define SM_B2 (SM_B1 + 256)             /* 128 f */
#define SM_TOTAL (SM_B2 + 512)

// ---------------------------------------------------------------------------
// Kernel 1: FPS (unchanged, measured 382us, bit-exact chain).
// ---------------------------------------------------------------------------
__global__ __launch_bounds__(256) void fps_kernel(const float* __restrict__ xyz,
                                                  float* __restrict__ out_xyz) {
    const int b = blockIdx.x;
    const float* x = xyz + (size_t)b * NN * 3;
    const int tid = threadIdx.x;
    const int lane = tid & 31, wid = tid >> 5;

    __shared__ float sxx[NN], sxy[NN], sxz[NN];
    __shared__ u64 skey[2][8];

    u64 pxp[8], pyp[8], pzp[8];
    float dmin[16];
#pragma unroll
    for (int p = 0; p < 8; p++) {
        int j = tid * 16 + 2 * p;
        pxp[p] = pack2(x[j * 3 + 0], x[j * 3 + 3]);
        pyp[p] = pack2(x[j * 3 + 1], x[j * 3 + 4]);
        pzp[p] = pack2(x[j * 3 + 2], x[j * 3 + 5]);
        dmin[2 * p] = 1e10f;
        dmin[2 * p + 1] = 1e10f;
    }
#pragma unroll
    for (int p = 0; p < 8; p++) {
        int j = tid * 16 + 2 * p;
        float a0, a1;
        unpack2(pxp[p], a0, a1); sxx[j] = a0; sxx[j + 1] = a1;
        unpack2(pyp[p], a0, a1); sxy[j] = a0; sxy[j + 1] = a1;
        unpack2(pzp[p], a0, a1); sxz[j] = a0; sxz[j + 1] = a1;
    }
    __syncthreads();

    float ccx = sxx[0], ccy = sxy[0], ccz = sxz[0];

    for (int i = 0; i < SS; i++) {
        const int par = i & 1;
        if (tid == 0) {
            float* o = out_xyz + ((size_t)b * SS + i) * 3;
            o[0] = ccx; o[1] = ccy; o[2] = ccz;
        }
        u64 cx2 = pack2(ccx, ccx);
        u64 cy2 = pack2(ccy, ccy);
        u64 cz2 = pack2(ccz, ccz);

        float bva = -1.0f, bvb = -1.0f;
#pragma unroll
        for (int p = 0; p < 8; p++) {
            u64 sx = sub2(pxp[p], cx2);
            u64 sy = sub2(pyp[p], cy2);
            u64 sz = sub2(pzp[p], cz2);
            u64 dd = add2(add2(mul2(sx, sx), mul2(sy, sy)), mul2(sz, sz));
            float d0, d1;
            unpack2(dd, d0, d1);
            dmin[2 * p] = fminf(dmin[2 * p], d0);
            dmin[2 * p + 1] = fminf(dmin[2 * p + 1], d1);
            bva = fmaxf(bva, dmin[2 * p]);
            bvb = fmaxf(bvb, dmin[2 * p + 1]);
        }
        float bv = fmaxf(bva, bvb);

        unsigned vb = __float_as_uint(bv);
        unsigned wm = __reduce_max_sync(0xffffffffu, vb);
        unsigned bal = __ballot_sync(0xffffffffu, vb == wm);
        int src = __ffs(bal) - 1;

        int ck = 0;
#pragma unroll
        for (int k = 15; k >= 1; k--)
            if (__float_as_uint(dmin[k]) == wm) ck = k;

        int gidx = (wid * 32 + src) * 16 + __shfl_sync(0xffffffffu, ck, src);
        if (lane == 0)
            skey[par][wid] = ((u64)wm << 32) | (unsigned)(4095 - gidx);
        __syncthreads();

        u64 k0 = skey[par][0], k1 = skey[par][1];
        u64 k2 = skey[par][2], k3 = skey[par][3];
        u64 k4 = skey[par][4], k5 = skey[par][5];
        u64 k6 = skey[par][6], k7 = skey[par][7];
        u64 mk = u64max(u64max(u64max(k0, k1), u64max(k2, k3)),
                        u64max(u64max(k4, k5), u64max(k6, k7)));
        int far = 4095 - (int)(unsigned)mk;

        ccx = sxx[far];
        ccy = sxy[far];
        ccz = sxz[far];
    }
}

// ---------------------------------------------------------------------------
// Kernel 2: ball query (unchanged).
// ---------------------------------------------------------------------------
__global__ __launch_bounds__(256) void qb_kernel(const float* __restrict__ xyz,
                                                 const float* __restrict__ new_xyz) {
    const int gw = (blockIdx.x * blockDim.x + threadIdx.x) >> 5;
    const int lane = threadIdx.x & 31;
    if (gw >= BB * SS) return;
    const int b = gw >> 10;
    const float* x = xyz + (size_t)b * NN * 3;
    const float cx = new_xyz[gw * 3 + 0];
    const float cy = new_xyz[gw * 3 + 1];
    const float cz = new_xyz[gw * 3 + 2];
    int* o = g_idx + (size_t)gw * KNB;

    const float r2 = 0.04f;
    int cnt = 0;
    int first = 0;
    bool have = false;
    for (int j0 = 0; j0 < NN; j0 += 32) {
        int j = j0 + lane;
        float dx = x[j * 3 + 0] - cx;
        float dy = x[j * 3 + 1] - cy;
        float dz = x[j * 3 + 2] - cz;
        float d = __fadd_rn(__fadd_rn(__fmul_rn(dx, dx), __fmul_rn(dy, dy)),
                            __fmul_rn(dz, dz));
        bool in = (d <= r2);
        unsigned m = __ballot_sync(0xffffffffu, in);
        if (!have && m) { first = j0 + __ffs(m) - 1; have = true; }
        int pre = __popc(m & ((1u << lane) - 1u));
        if (in) {
            int p = cnt + pre;
            if (p < KNB) o[p] = j;
        }
        cnt += __popc(m);
        if (cnt >= KNB) break;
    }
    for (int p = cnt + lane; p < KNB; p += 32) o[p] = first;
}

// ---------------------------------------------------------------------------
// Kernel W: pre-split weights into the packed [n][k] bf16 image (hi/lo).
// Row n = output feature (64 or 128), col k = input channel (64), stride 136B.
// ---------------------------------------------------------------------------
__global__ void winit_kernel(const float* __restrict__ w0,
                             const float* __restrict__ w1,
                             const float* __restrict__ w2) {
    int idx = blockIdx.x * blockDim.x + threadIdx.x;
    if (idx >= 16384) return;
    int n, k, rh, rl;
    float v;
    if (idx < 4096) {
        n = idx & 63; k = idx >> 6; v = w0[k * 64 + n]; rh = W_S0H; rl = W_S0L;
    } else if (idx < 8192) {
        int t = idx - 4096;
        n = t & 63; k = t >> 6; v = w1[k * 64 + n]; rh = W_S1H; rl = W_S1L;
    } else {
        int t = idx - 8192;
        n = t & 127; k = t >> 7; v = w2[k * 128 + n]; rh = W_S2H; rl = W_S2L;
    }
    unsigned short h, l;
    split_bf16(v, h, l);
    *reinterpret_cast<unsigned short*>(g_wimg + rh + n * W_STRIDE + k * 2) = h;
    *reinterpret_cast<unsigned short*>(g_wimg + rl + n * W_STRIDE + k * 2) = l;
}

// ---------------------------------------------------------------------------
// A-fragment load: 2 m-tiles x 4 k-steps x 4 regs from A (row r0..r0+31).
// ---------------------------------------------------------------------------
__device__ __forceinline__ void load_frags(const char* A, int r0, int lane,
                                           uint32_t f[2][4][4]) {
    const int tig = lane & 3, gid = lane >> 2;
#pragma unroll
    for (int mt = 0; mt < 2; mt++) {
        const char* rlo = A + (r0 + 16 * mt + gid) * A_STRIDE + 4 * tig;
        const char* rhi = rlo + 8 * A_STRIDE;
#pragma unroll
        for (int ks = 0; ks < 4; ks++) {
            f[mt][ks][0] = *(const uint32_t*)(rlo + 32 * ks);
            f[mt][ks][1] = *(const uint32_t*)(rhi + 32 * ks);
            f[mt][ks][2] = *(const uint32_t*)(rlo + 32 * ks + 16);
            f[mt][ks][3] = *(const uint32_t*)(rhi + 32 * ks + 16);
        }
    }
}

__device__ __forceinline__ void relu_split_store(char* Ahi, char* Alo, int row,
                                                 int cb, float v0, float v1) {
    v0 = fmaxf(v0, 0.0f);
    v1 = fmaxf(v1, 0.0f);
    unsigned short h0, l0, h1, l1;
    split_bf16(v0, h0, l0);
    split_bf16(v1, h1, l1);
    *(uint32_t*)(Ahi + row * A_STRIDE + cb) = (uint32_t)h0 | ((uint32_t)h1 << 16);
    *(uint32_t*)(Alo + row * A_STRIDE + cb) = (uint32_t)l0 | ((uint32_t)l1 << 16);
}

// ---------------------------------------------------------------------------
// One MLP stage on tensor cores. NT n-tiles of 8. XYZ: fold rel-xyz into init.
// POOL: maxpool epilogue. Warp-private (rows r0..r0+31).
// ---------------------------------------------------------------------------
template <int NT, bool XYZ, bool POOL>
__device__ __forceinline__ void mma_stage(
    char* sm, int woff_h, int woff_l, const uint32_t ah[2][4][4],
    const uint32_t al[2][4][4], const float* bias, const float* wx,
    const float* wy, const float* wz, const float rxv[2][2],
    const float ryv[2][2], const float rzv[2][2], char* Ahi, char* Alo,
    float* outp, int r0, int lane) {
    const int tig = lane & 3, gid = lane >> 2;
    const char* Wh = sm + SM_W + woff_h;
    const char* Wl = sm + SM_W + woff_l;

#pragma unroll
    for (int ntp = 0; ntp < NT / 2; ntp++) {
        float acc[2][2][4];
#pragma unroll
        for (int ntq = 0; ntq < 2; ntq++) {
            const int col0 = (2 * ntp + ntq) * 8 + 2 * tig;
            const float bb0 = bias[col0], bb1 = bias[col0 + 1];
            if (XYZ) {
                const float wx0 = wx[col0], wx1 = wx[col0 + 1];
                const float wy0 = wy[col0], wy1 = wy[col0 + 1];
                const float wz0 = wz[col0], wz1 = wz[col0 + 1];
#pragma unroll
                for (int mt = 0; mt < 2; mt++) {
                    acc[ntq][mt][0] =
                        bb0 + rxv[mt][0] * wx0 + ryv[mt][0] * wy0 + rzv[mt][0] * wz0;
                    acc[ntq][mt][1] =
                        bb1 + rxv[mt][0] * wx1 + ryv[mt][0] * wy1 + rzv[mt][0] * wz1;
                    acc[ntq][mt][2] =
                        bb0 + rxv[mt][1] * wx0 + ryv[mt][1] * wy0 + rzv[mt][1] * wz0;
                    acc[ntq][mt][3] =
                        bb1 + rxv[mt][1] * wx1 + ryv[mt][1] * wy1 + rzv[mt][1] * wz1;
                }
            } else {
#pragma unroll
                for (int mt = 0; mt < 2; mt++) {
                    acc[ntq][mt][0] = bb0;
                    acc[ntq][mt][1] = bb1;
                    acc[ntq][mt][2] = bb0;
                    acc[ntq][mt][3] = bb1;
                }
            }
        }
#pragma unroll
        for (int ks = 0; ks < 4; ks++) {
#pragma unroll
            for (int ntq = 0; ntq < 2; ntq++) {
                const int n = (2 * ntp + ntq) * 8 + gid;
                const char* ph = Wh + n * W_STRIDE + 4 * tig + 32 * ks;
                const char* pl = Wl + n * W_STRIDE + 4 * tig + 32 * ks;
                uint32_t bh0 = *(const uint32_t*)ph;
                uint32_t bh1 = *(const uint32_t*)(ph + 16);
                uint32_t bl0 = *(const uint32_t*)pl;
                uint32_t bl1 = *(const uint32_t*)(pl + 16);
#pragma unroll
                for (int mt = 0; mt < 2; mt++) {
                    mma16816(acc[ntq][mt], ah[mt][ks], bh0, bh1);
                    mma16816(acc[ntq][mt], al[mt][ks], bh0, bh1);
                    mma16816(acc[ntq][mt], ah[mt][ks], bl0, bl1);
                }
            }
        }
        // epilogue
#pragma unroll
        for (int ntq = 0; ntq < 2; ntq++) {
            const int col0 = (2 * ntp + ntq) * 8 + 2 * tig;
            if (POOL) {
                float m0 = fmaxf(fmaxf(fmaxf(acc[ntq][0][0], 0.0f),
                                       fmaxf(acc[ntq][0][2], 0.0f)),
                                 fmaxf(fmaxf(acc[ntq][1][0], 0.0f),
                                       fmaxf(acc[ntq][1][2], 0.0f)));
                float m1 = fmaxf(fmaxf(fmaxf(acc[ntq][0][1], 0.0f),
                                       fmaxf(acc[ntq][0][3], 0.0f)),
                                 fmaxf(fmaxf(acc[ntq][1][1], 0.0f),
                                       fmaxf(acc[ntq][1][3], 0.0f)));
#pragma unroll
                for (int s = 4; s <= 16; s <<= 1) {
                    m0 = fmaxf(m0, __shfl_xor_sync(0xffffffffu, m0, s));
                    m1 = fmaxf(m1, __shfl_xor_sync(0xffffffffu, m1, s));
                }
                if (gid == 0) *(float2*)(outp + col0) = make_float2(m0, m1);
            } else {
                const int cb = col0 * 2;
#pragma unroll
                for (int mt = 0; mt < 2; mt++) {
                    const int rlo = r0 + 16 * mt + gid;
                    relu_split_store(Ahi, Alo, rlo, cb, acc[ntq][mt][0],
                                     acc[ntq][mt][1]);
                    relu_split_store(Ahi, Alo, rlo + 8, cb, acc[ntq][mt][2],
                                     acc[ntq][mt][3]);
                }
            }
        }
    }
}

// ---------------------------------------------------------------------------
// Kernel 3: tensor-core MLP via mma.sync. 4 sites/CTA, warp = site.
// ---------------------------------------------------------------------------
__global__ __launch_bounds__(128) void mlp_kernel(
    const float* __restrict__ xyz, const float* __restrict__ points,
    const float* __restrict__ new_xyz, const float* __restrict__ w0,
    const float* __restrict__ b0, const float* __restrict__ b1,
    const float* __restrict__ b2, float* __restrict__ out_points) {
    extern __shared__ __align__(16) char sm[];
    const int tid = threadIdx.x;
    const int lane = tid & 31, wid = tid >> 5;
    const int gw0 = blockIdx.x * 4;
    const int b = gw0 >> 10;

    char* Ahi = sm + SM_AHI;
    char* Alo = sm + SM_ALO;
    float* rxs = (float*)(sm + SM_RX);
    float* rys = (float*)(sm + SM_RY);
    float* rzs = (float*)(sm + SM_RZ);

    // weight image -> smem
    {
        const uint4* src = (const uint4*)g_wimg;
        uint4* dst = (uint4*)(sm + SM_W);
#pragma unroll
        for (int it = 0; it < 34; it++) dst[tid + it * 128] = src[tid + it * 128];
    }
    if (tid < 64) {
        ((float*)(sm + SM_WX))[tid] = w0[64 * 64 + tid];
        ((float*)(sm + SM_WY))[tid] = w0[65 * 64 + tid];
        ((float*)(sm + SM_WZ))[tid] = w0[66 * 64 + tid];
        ((float*)(sm + SM_B0))[tid] = b0[tid];
        ((float*)(sm + SM_B1))[tid] = b1[tid];
    }
    ((float*)(sm + SM_B2))[tid] = b2[tid];

    // gather: thread = row r; warp-private rows
    {
        const int r = tid;
        const int site = r >> 5;
        const int id = g_idx[(size_t)(gw0 + site) * KNB + (r & 31)];
        const float* c = new_xyz + (size_t)(gw0 + site) * 3;
        const float* p = xyz + ((size_t)b * NN + id) * 3;
        rxs[r] = p[0] - c[0];
        rys[r] = p[1] - c[1];
        rzs[r] = p[2] - c[2];
        const float4* pf =
            (const float4*)(points + ((size_t)b * NN + id) * CC);
        char* rowh = Ahi + r * A_STRIDE;
        char* rowl = Alo + r * A_STRIDE;
#pragma unroll
        for (int i = 0; i < 16; i++) {
            float4 v = pf[i];
            unsigned short h0, l0, h1, l1, h2, l2, h3, l3;
            split_bf16(v.x, h0, l0); split_bf16(v.y, h1, l1);
            split_bf16(v.z, h2, l2); split_bf16(v.w, h3, l3);
            *(u64*)(rowh + 8 * i) =
                (u64)h0 | ((u64)h1 << 16) | ((u64)h2 << 32) | ((u64)h3 << 48);
            *(u64*)(rowl + 8 * i) =
                (u64)l0 | ((u64)l1 << 16) | ((u64)l2 << 32) | ((u64)l3 << 48);
        }
    }
    __syncthreads();  // weights + consts visible (gather is warp-private)

    const int r0 = wid * 32;
    const int gid = lane >> 2;

    // per-row rel-xyz for D-init (rows of my m-tiles)
    float rxv[2][2], ryv[2][2], rzv[2][2];
#pragma unroll
    for (int mt = 0; mt < 2; mt++) {
        int rlo = r0 + 16 * mt + gid;
        rxv[mt][0] = rxs[rlo]; rxv[mt][1] = rxs[rlo + 8];
        ryv[mt][0] = rys[rlo]; ryv[mt][1] = rys[rlo + 8];
        rzv[mt][0] = rzs[rlo]; rzv[mt][1] = rzs[rlo + 8];
    }

    uint32_t ah[2][4][4], al[2][4][4];

    // stage 0: 67 -> 64
    load_frags(Ahi, r0, lane, ah);
    load_frags(Alo, r0, lane, al);
    __syncwarp();
    mma_stage<8, true, false>(sm, W_S0H, W_S0L, ah, al, (float*)(sm + SM_B0),
                              (float*)(sm + SM_WX), (float*)(sm + SM_WY),
                              (float*)(sm + SM_WZ), rxv, ryv, rzv, Ahi, Alo,
                              nullptr, r0, lane);
    __syncwarp();

    // stage 1: 64 -> 64
    load_frags(Ahi, r0, lane, ah);
    load_frags(Alo, r0, lane, al);
    __syncwarp();
    mma_stage<8, false, false>(sm, W_S1H, W_S1L, ah, al, (float*)(sm + SM_B1),
                               nullptr, nullptr, nullptr, rxv, ryv, rzv, Ahi,
                               Alo, nullptr, r0, lane);
    __syncwarp();

    // stage 2: 64 -> 128 + maxpool
    load_frags(Ahi, r0, lane, ah);
    load_frags(Alo, r0, lane, al);
    __syncwarp();
    mma_stage<16, false, true>(sm, W_S2H, W_S2L, ah, al, (float*)(sm + SM_B2),
                               nullptr, nullptr, nullptr, rxv, ryv, rzv, Ahi,
                               Alo, out_points + (size_t)(gw0 + wid) * 128, r0,
                               lane);
}

extern "C" void kernel_launch(void* const* d_in, const int* in_sizes, int n_in,
                              void* d_out, int out_size) {
    const float* xyz = (const float*)d_in[0];
    const float* points = (const float*)d_in[1];
    const float* w0 = (const float*)d_in[2];
    const float* b0 = (const float*)d_in[3];
    const float* w1 = (const float*)d_in[4];
    const float* b1 = (const float*)d_in[5];
    const float* w2 = (const float*)d_in[6];
    const float* b2 = (const float*)d_in[7];

    float* out = (float*)d_out;
    float* new_xyz = out;                   // [B, S, 3]
    float* new_points = out + BB * SS * 3;  // [B, S, 128]

    static int smem_set = 0;
    if (!smem_set) {
        cudaFuncSetAttribute(mlp_kernel,
                             cudaFuncAttributeMaxDynamicSharedMemorySize,
                             SM_TOTAL);
        smem_set = 1;
    }

    fps_kernel<<<BB, 256>>>(xyz, new_xyz);
    winit_kernel<<<64, 256>>>(w0, w1, w2);
    qb_kernel<<<(BB * SS * 32 + 255) / 256, 256>>>(xyz, new_xyz);
    mlp_kernel<<<BB * SS / 4, 128, SM_TOTAL>>>(xyz, points, new_xyz, w0, b0,
                                               b1, b2, new_points);
}